// round 1
// baseline (speedup 1.0000x reference)
#include <cuda_runtime.h>
#include <math.h>

#define B   16
#define S   1024
#define NF  5
#define D   64
#define H   8
#define HD  8
#define NL  2
#define FF  128
#define NQ  8
#define QL  3
#define BS  (B*S)

// ---------------- device scratch (static allocation only) ----------------
__device__ float g_h  [BS*D];
__device__ float g_q  [BS*D];
__device__ float g_k  [BS*D];
__device__ float g_v  [BS*D];
__device__ float g_ao [BS*D];
__device__ float g_ffh[BS*FF];
__device__ float g_angles[B*NQ];

// ---------------- complex helpers ----------------
__device__ __forceinline__ float2 cmul(float2 a, float2 b) {
    return make_float2(a.x*b.x - a.y*b.y, a.x*b.y + a.y*b.x);
}
__device__ __forceinline__ float2 cmulcj(float2 a, float2 b) { // conj(a)*b
    return make_float2(a.x*b.x + a.y*b.y, a.x*b.y - a.y*b.x);
}
__device__ __forceinline__ float2 cadd(float2 a, float2 b) {
    return make_float2(a.x + b.x, a.y + b.y);
}

// ---------------- 1) embedding + positional encoding ----------------
__global__ void k_embed(const float* __restrict__ x,
                        const float* __restrict__ Wemb,
                        const float* __restrict__ bemb) {
    int idx = blockIdx.x * blockDim.x + threadIdx.x;   // < BS*D
    int c   = idx & (D-1);
    int row = idx >> 6;
    int s   = row & (S-1);
    float acc = bemb[c];
    const float* xr = x + row * NF;
#pragma unroll
    for (int f = 0; f < NF; f++) acc += xr[f] * Wemb[f*D + c];
    int i2 = (c >> 1) * 2;
    float div = expf((float)i2 * (-0.14391156831212787f));  // -ln(10000)/64
    float arg = (float)s * div;
    acc += (c & 1) ? cosf(arg) : sinf(arg);
    g_h[idx] = acc;
}

// ---------------- 2) fused QKV projection ----------------
__global__ void k_qkv(const float* __restrict__ Wq, const float* __restrict__ bq,
                      const float* __restrict__ Wk, const float* __restrict__ bk,
                      const float* __restrict__ Wv, const float* __restrict__ bv,
                      int l) {
    extern __shared__ float sm[];
    float* sWq  = sm;
    float* sWk  = sm + 4096;
    float* sWv  = sm + 8192;
    float* srow = sm + 12288;         // 256 floats
    int tid = threadIdx.x;
    const float* wq = Wq + l*4096;
    const float* wk = Wk + l*4096;
    const float* wv = Wv + l*4096;
    for (int i = tid; i < 4096; i += 256) { sWq[i]=wq[i]; sWk[i]=wk[i]; sWv[i]=wv[i]; }
    int base = blockIdx.x * 64;
    int r = tid >> 6, c = tid & 63;
    float bqv = bq[l*D+c], bkv = bk[l*D+c], bvv = bv[l*D+c];
    __syncthreads();
    for (int g = 0; g < 16; g++) {
        int row0 = base + g*4;
        srow[tid] = g_h[row0*D + tid];     // 4 contiguous rows
        __syncthreads();
        float aq = bqv, ak = bkv, av = bvv;
        const float* hr = srow + r*64;
#pragma unroll
        for (int i = 0; i < 64; i++) {
            float hv = hr[i];
            aq += hv * sWq[i*64 + c];
            ak += hv * sWk[i*64 + c];
            av += hv * sWv[i*64 + c];
        }
        int row = row0 + r;
        g_q[row*D + c] = aq;
        g_k[row*D + c] = ak;
        g_v[row*D + c] = av;
        __syncthreads();
    }
}

// ---------------- 3) attention (flash-style, online softmax) ----------------
__global__ void k_attn() {
    extern __shared__ float sm[];
    float* sK = sm;             // 1024*8
    float* sV = sm + S*HD;      // 1024*8
    int tid = threadIdx.x;
    int bh  = blockIdx.y;
    int b   = bh >> 3, hh = bh & 7;
    const float* kbase = g_k + (size_t)(b*S)*D + hh*HD;
    const float* vbase = g_v + (size_t)(b*S)*D + hh*HD;
    for (int t = tid; t < S*HD; t += 256) {
        int s = t >> 3, d = t & 7;
        sK[t] = kbase[s*D + d];
        sV[t] = vbase[s*D + d];
    }
    __syncthreads();

    int qi = blockIdx.x * 256 + tid;
    const float* qp = g_q + (size_t)(b*S + qi)*D + hh*HD;
    float q0=qp[0], q1=qp[1], q2=qp[2], q3=qp[3], q4=qp[4], q5=qp[5], q6=qp[6], q7=qp[7];

    float m = -1e30f, lsum = 0.f;
    float a0=0,a1=0,a2=0,a3=0,a4=0,a5=0,a6=0,a7=0;
    const float4* K4 = (const float4*)sK;
    const float4* V4 = (const float4*)sV;
    const float scale = 0.35355339059327373f;  // 1/sqrt(8)

    for (int j = 0; j < S; j++) {
        float4 ka = K4[j*2], kb = K4[j*2+1];
        float x = q0*ka.x + q1*ka.y + q2*ka.z + q3*ka.w
                + q4*kb.x + q5*kb.y + q6*kb.z + q7*kb.w;
        x *= scale;
        if (x > m) {
            float corr = __expf(m - x);
            lsum *= corr;
            a0*=corr; a1*=corr; a2*=corr; a3*=corr;
            a4*=corr; a5*=corr; a6*=corr; a7*=corr;
            m = x;
        }
        float w = __expf(x - m);
        lsum += w;
        float4 va = V4[j*2], vb = V4[j*2+1];
        a0 += w*va.x; a1 += w*va.y; a2 += w*va.z; a3 += w*va.w;
        a4 += w*vb.x; a5 += w*vb.y; a6 += w*vb.z; a7 += w*vb.w;
    }
    float inv = 1.0f / lsum;
    float* op = g_ao + (size_t)(b*S + qi)*D + hh*HD;
    op[0]=a0*inv; op[1]=a1*inv; op[2]=a2*inv; op[3]=a3*inv;
    op[4]=a4*inv; op[5]=a5*inv; op[6]=a6*inv; op[7]=a7*inv;
}

// ---------------- 4) output projection + residual + LayerNorm1 ----------------
__global__ void k_oproj_ln(const float* __restrict__ Wo, const float* __restrict__ bo,
                           const float* __restrict__ g1, const float* __restrict__ b1,
                           int l) {
    __shared__ float sW[4096];
    __shared__ float satt[256];
    __shared__ float sval[256];
    int tid = threadIdx.x;
    const float* w = Wo + l*4096;
    for (int i = tid; i < 4096; i += 256) sW[i] = w[i];
    int base = blockIdx.x * 64;
    int r = tid >> 6, c = tid & 63;
    float bov = bo[l*D+c], gv = g1[l*D+c], bv = b1[l*D+c];
    __syncthreads();
    for (int g = 0; g < 16; g++) {
        int row0 = base + g*4;
        satt[tid] = g_ao[row0*D + tid];
        __syncthreads();
        float acc = bov;
        const float* ar = satt + r*64;
#pragma unroll
        for (int i = 0; i < 64; i++) acc += ar[i] * sW[i*64 + c];
        int row = row0 + r;
        float val = acc + g_h[row*D + c];
        sval[tid] = val;
        __syncthreads();
        float sum = 0.f, sq = 0.f;
        const float* vr = sval + r*64;
#pragma unroll
        for (int i = 0; i < 64; i++) { float t = vr[i]; sum += t; sq += t*t; }
        float mean = sum * (1.f/64.f);
        float var  = sq  * (1.f/64.f) - mean*mean;
        g_h[row*D + c] = (val - mean) * rsqrtf(var + 1e-5f) * gv + bv;
        __syncthreads();
    }
}

// ---------------- 5) FFN first matmul + ReLU ----------------
__global__ void k_ffn1(const float* __restrict__ Wf1, const float* __restrict__ bf1, int l) {
    __shared__ float sW[64*128];
    __shared__ float srow[128];
    int tid = threadIdx.x;
    const float* w = Wf1 + l*8192;
    for (int i = tid; i < 8192; i += 256) sW[i] = w[i];
    int base = blockIdx.x * 64;
    int r = tid >> 7, j = tid & 127;
    float bfv = bf1[l*FF + j];
    __syncthreads();
    for (int g = 0; g < 32; g++) {
        int row0 = base + g*2;
        if (tid < 128) srow[tid] = g_h[row0*D + tid];
        __syncthreads();
        float acc = bfv;
        const float* hr = srow + r*64;
#pragma unroll
        for (int i = 0; i < 64; i++) acc += hr[i] * sW[i*128 + j];
        g_ffh[(row0 + r)*FF + j] = fmaxf(acc, 0.f);
        __syncthreads();
    }
}

// ---------------- 6) FFN second matmul + residual + LayerNorm2 ----------------
__global__ void k_ffn2_ln(const float* __restrict__ Wf2, const float* __restrict__ bf2,
                          const float* __restrict__ g2, const float* __restrict__ b2,
                          int l) {
    __shared__ float sW[128*64];
    __shared__ float shid[512];
    __shared__ float sval[256];
    int tid = threadIdx.x;
    const float* w = Wf2 + l*8192;
    for (int i = tid; i < 8192; i += 256) sW[i] = w[i];
    int base = blockIdx.x * 64;
    int r = tid >> 6, c = tid & 63;
    float bfv = bf2[l*D+c], gv = g2[l*D+c], bv = b2[l*D+c];
    __syncthreads();
    for (int g = 0; g < 16; g++) {
        int row0 = base + g*4;
        shid[tid]       = g_ffh[row0*FF + tid];
        shid[tid + 256] = g_ffh[row0*FF + tid + 256];
        __syncthreads();
        float acc = bfv;
        const float* hr = shid + r*128;
#pragma unroll
        for (int i = 0; i < 128; i++) acc += hr[i] * sW[i*64 + c];
        int row = row0 + r;
        float val = acc + g_h[row*D + c];
        sval[tid] = val;
        __syncthreads();
        float sum = 0.f, sq = 0.f;
        const float* vr = sval + r*64;
#pragma unroll
        for (int i = 0; i < 64; i++) { float t = vr[i]; sum += t; sq += t*t; }
        float mean = sum * (1.f/64.f);
        float var  = sq  * (1.f/64.f) - mean*mean;
        g_h[row*D + c] = (val - mean) * rsqrtf(var + 1e-5f) * gv + bv;
        __syncthreads();
    }
}

// ---------------- 7) mean pool + MLP head -> angles ----------------
__global__ void k_pool_mlp(const float* __restrict__ Wp1, const float* __restrict__ bp1,
                           const float* __restrict__ Wp2, const float* __restrict__ bp2) {
    __shared__ float sp[64];
    __shared__ float sh[32];
    int b = blockIdx.x, tid = threadIdx.x;
    const float* hb = g_h + (size_t)b*S*D;
    float sum = 0.f;
#pragma unroll 4
    for (int s = 0; s < S; s++) sum += hb[s*D + tid];
    sp[tid] = sum * (1.0f/(float)S);
    __syncthreads();
    if (tid < 32) {
        float a = bp1[tid];
#pragma unroll
        for (int i = 0; i < 64; i++) a += sp[i] * Wp1[i*32 + tid];
        sh[tid] = fmaxf(a, 0.f);
    }
    __syncthreads();
    if (tid < 8) {
        float a = bp2[tid];
#pragma unroll
        for (int i = 0; i < 32; i++) a += sh[i] * Wp2[i*8 + tid];
        g_angles[b*NQ + tid] = tanhf(a) * 3.14159265358979f;
    }
}

// ---------------- 8) quantum circuit + <Z> + von Neumann entropy ----------------
__global__ void k_quantum(const float* __restrict__ qw, float* __restrict__ out) {
    __shared__ float2 st[256];
    __shared__ float2 rho[256];
    __shared__ float  sred[256];
    int b = blockIdx.x, tid = threadIdx.x;

    st[tid] = make_float2(tid == 0 ? 1.f : 0.f, 0.f);
    float ang[NQ];
#pragma unroll
    for (int w = 0; w < NQ; w++) ang[w] = g_angles[b*NQ + w];

    for (int l = 0; l < QL; l++) {
        // RX(angle[w]) on each wire
        for (int w = 0; w < NQ; w++) {
            int mask = 1 << (7 - w);
            float c = cosf(0.5f * ang[w]);
            float s = sinf(0.5f * ang[w]);
            __syncthreads();
            if (!(tid & mask)) {
                float2 v0 = st[tid], v1 = st[tid | mask];
                // U = [[c, -i s], [-i s, c]]
                st[tid]        = make_float2(c*v0.x + s*v1.y,  c*v0.y - s*v1.x);
                st[tid | mask] = make_float2(s*v0.y + c*v1.x, -s*v0.x + c*v1.y);
            }
        }
        // Rot(phi, th, om) = RZ(om) RY(th) RZ(phi)
        for (int w = 0; w < NQ; w++) {
            int mask = 1 << (7 - w);
            float phi = qw[(l*NQ + w)*3 + 0];
            float th  = qw[(l*NQ + w)*3 + 1];
            float om  = qw[(l*NQ + w)*3 + 2];
            float ct = cosf(0.5f*th), stt = sinf(0.5f*th);
            float aa = 0.5f*(phi + om), bb = 0.5f*(phi - om);
            float ca = cosf(aa), sa = sinf(aa), cb = cosf(bb), sb = sinf(bb);
            float2 U00 = make_float2( ct*ca, -ct*sa);
            float2 U01 = make_float2(-stt*cb, -stt*sb);
            float2 U10 = make_float2( stt*cb, -stt*sb);
            float2 U11 = make_float2( ct*ca,  ct*sa);
            __syncthreads();
            if (!(tid & mask)) {
                float2 v0 = st[tid], v1 = st[tid | mask];
                st[tid]        = cadd(cmul(U00, v0), cmul(U01, v1));
                st[tid | mask] = cadd(cmul(U10, v0), cmul(U11, v1));
            }
        }
        // CNOT ring
        for (int w = 0; w < NQ; w++) {
            int mc = 1 << (7 - w);
            int mt = 1 << (7 - ((w + 1) & 7));
            __syncthreads();
            if ((tid & mc) && !(tid & mt)) {
                float2 t0 = st[tid];
                st[tid] = st[tid | mt];
                st[tid | mt] = t0;
            }
        }
    }
    __syncthreads();

    // <Z_w> for w = 0..2
    float p = st[tid].x*st[tid].x + st[tid].y*st[tid].y;
    for (int w = 0; w < 3; w++) {
        sred[tid] = (tid & (1 << (7 - w))) ? -p : p;
        __syncthreads();
        for (int off = 128; off > 0; off >>= 1) {
            if (tid < off) sred[tid] += sred[tid + off];
            __syncthreads();
        }
        if (tid == 0) out[b*3 + w] = sred[0];
        __syncthreads();
    }

    // reduced density matrix rho = mat @ mat^H, mat = psi.reshape(16,16)
    {
        int r = tid >> 4, c = tid & 15;
        float2 acc = make_float2(0.f, 0.f);
#pragma unroll
        for (int k = 0; k < 16; k++) {
            float2 mr = st[r*16 + k], mcv = st[c*16 + k];
            acc.x += mr.x*mcv.x + mr.y*mcv.y;   // mr * conj(mcv)
            acc.y += mr.y*mcv.x - mr.x*mcv.y;
        }
        rho[tid] = acc;
    }
    __syncthreads();

    // cyclic complex Jacobi (warp 0, 16 lanes do columns), 6 sweeps
    if (tid < 32) {
        int lane = tid;
        for (int sweep = 0; sweep < 6; sweep++) {
            for (int pp = 0; pp < 15; pp++) {
                for (int qq = pp + 1; qq < 16; qq++) {
                    float2 apq = rho[pp*16 + qq];
                    float b2 = apq.x*apq.x + apq.y*apq.y;
                    if (b2 > 1e-26f) {
                        float app = rho[pp*16 + pp].x;
                        float aqq = rho[qq*16 + qq].x;
                        float bn  = sqrtf(b2);
                        float tau = (aqq - app) / (2.f * bn);
                        float rt  = sqrtf(1.f + tau*tau);
                        float t   = (tau >= 0.f) ? 1.f/(tau + rt) : -1.f/(-tau + rt);
                        float cc  = rsqrtf(1.f + t*t);
                        float ss  = t * cc;
                        float2 ph = make_float2(apq.x/bn, apq.y/bn);   // e^{i theta}
                        if (lane < 16) {
                            int k = lane;
                            float2 rp = rho[pp*16 + k], rq = rho[qq*16 + k];
                            float2 prq  = cmul(ph, rq);      // e^{i t} * rq
                            float2 cprp = cmulcj(ph, rp);    // e^{-i t} * rp
                            rho[pp*16 + k] = make_float2(cc*rp.x - ss*prq.x,  cc*rp.y - ss*prq.y);
                            rho[qq*16 + k] = make_float2(ss*cprp.x + cc*rq.x, ss*cprp.y + cc*rq.y);
                        }
                        __syncwarp();
                        if (lane < 16) {
                            int k = lane;
                            float2 cp = rho[k*16 + pp], cq = rho[k*16 + qq];
                            float2 ccq = cmulcj(ph, cq);     // e^{-i t} * cq
                            float2 pcp = cmul(ph, cp);       // e^{i t} * cp
                            rho[k*16 + pp] = make_float2(cc*cp.x - ss*ccq.x,  cc*cp.y - ss*ccq.y);
                            rho[k*16 + qq] = make_float2(ss*pcp.x + cc*cq.x, ss*pcp.y + cc*cq.y);
                        }
                        __syncwarp();
                    }
                }
            }
        }
        if (lane == 0) {
            float ent = 0.f;
#pragma unroll
            for (int k = 0; k < 16; k++) {
                float ev = rho[k*16 + k].x;
                ev = fminf(fmaxf(ev, 1e-10f), 1.f);
                ent -= ev * logf(ev);
            }
            out[48 + b] = ent;
        }
    }
}

// ---------------- launch ----------------
extern "C" void kernel_launch(void* const* d_in, const int* in_sizes, int n_in,
                              void* d_out, int out_size) {
    const float* x    = (const float*)d_in[0];
    const float* Wemb = (const float*)d_in[1];
    const float* bemb = (const float*)d_in[2];
    const float* Wq   = (const float*)d_in[3];
    const float* bq   = (const float*)d_in[4];
    const float* Wk   = (const float*)d_in[5];
    const float* bk   = (const float*)d_in[6];
    const float* Wv   = (const float*)d_in[7];
    const float* bv   = (const float*)d_in[8];
    const float* Wo   = (const float*)d_in[9];
    const float* bo   = (const float*)d_in[10];
    const float* ln1g = (const float*)d_in[11];
    const float* ln1b = (const float*)d_in[12];
    const float* ln2g = (const float*)d_in[13];
    const float* ln2b = (const float*)d_in[14];
    const float* Wf1  = (const float*)d_in[15];
    const float* bf1  = (const float*)d_in[16];
    const float* Wf2  = (const float*)d_in[17];
    const float* bf2  = (const float*)d_in[18];
    const float* Wp1  = (const float*)d_in[19];
    const float* bp1  = (const float*)d_in[20];
    const float* Wp2  = (const float*)d_in[21];
    const float* bp2  = (const float*)d_in[22];
    const float* qw   = (const float*)d_in[23];
    float* out = (float*)d_out;

    cudaFuncSetAttribute(k_attn, cudaFuncAttributeMaxDynamicSharedMemorySize, 65536);
    cudaFuncSetAttribute(k_qkv,  cudaFuncAttributeMaxDynamicSharedMemorySize, 50176);

    k_embed<<<(BS*D)/256, 256>>>(x, Wemb, bemb);
    for (int l = 0; l < NL; l++) {
        k_qkv<<<256, 256, 50176>>>(Wq, bq, Wk, bk, Wv, bv, l);
        dim3 ag(S/256, B*H);
        k_attn<<<ag, 256, 65536>>>();
        k_oproj_ln<<<256, 256>>>(Wo, bo, ln1g, ln1b, l);
        k_ffn1<<<256, 256>>>(Wf1, bf1, l);
        k_ffn2_ln<<<256, 256>>>(Wf2, bf2, ln2g, ln2b, l);
    }
    k_pool_mlp<<<B, 64>>>(Wp1, bp1, Wp2, bp2);
    k_quantum<<<B, 256>>>(qw, out);
}

// round 2
// speedup vs baseline: 1.9938x; 1.9938x over previous
#include <cuda_runtime.h>
#include <math.h>

#define B   16
#define S   1024
#define NF  5
#define D   64
#define H   8
#define HD  8
#define NL  2
#define FF  128
#define NQ  8
#define QL  3
#define BS  (B*S)

typedef unsigned long long ull;

// ---------------- device scratch ----------------
__device__ float g_h  [BS*D];
__device__ float g_q  [BS*D];
__device__ float g_k  [BS*D];
__device__ float g_v  [BS*D];
__device__ float g_ao [BS*D];
__device__ float g_ffh[BS*FF];
__device__ float g_pe [S*D];
__device__ float g_angles[B*NQ];

// ---------------- packed f32x2 helpers ----------------
__device__ __forceinline__ ull ffma2(ull a, ull b, ull c) {
    ull d; asm("fma.rn.f32x2 %0, %1, %2, %3;" : "=l"(d) : "l"(a), "l"(b), "l"(c)); return d;
}
__device__ __forceinline__ ull fmul2(ull a, ull b) {
    ull d; asm("mul.rn.f32x2 %0, %1, %2;" : "=l"(d) : "l"(a), "l"(b)); return d;
}
__device__ __forceinline__ ull fpack2(float lo, float hi) {
    ull d; asm("mov.b64 %0, {%1, %2};" : "=l"(d) : "f"(lo), "f"(hi)); return d;
}
__device__ __forceinline__ void funpack2(ull v, float& lo, float& hi) {
    asm("mov.b64 {%0, %1}, %2;" : "=f"(lo), "=f"(hi) : "l"(v));
}
__device__ __forceinline__ float fex2(float x) {
    float r; asm("ex2.approx.f32 %0, %1;" : "=f"(r) : "f"(x)); return r;
}

// ---------------- complex helpers ----------------
__device__ __forceinline__ float2 cmul(float2 a, float2 b) {
    return make_float2(a.x*b.x - a.y*b.y, a.x*b.y + a.y*b.x);
}
__device__ __forceinline__ float2 cmulcj(float2 a, float2 b) { // conj(a)*b
    return make_float2(a.x*b.x + a.y*b.y, a.x*b.y - a.y*b.x);
}
__device__ __forceinline__ float2 cadd(float2 a, float2 b) {
    return make_float2(a.x + b.x, a.y + b.y);
}

// ---------------- 0) positional-encoding table ----------------
__global__ void k_pe() {
    int idx = blockIdx.x * blockDim.x + threadIdx.x;   // < 32768
    int s = idx >> 5, p = idx & 31;
    float div = __expf(-0.14391156831212787f * (float)(2*p));
    float sn, cs;
    sincosf((float)s * div, &sn, &cs);
    g_pe[s*64 + 2*p]     = sn;
    g_pe[s*64 + 2*p + 1] = cs;
}

// ---------------- 1) embedding ----------------
__global__ void k_embed(const float* __restrict__ x,
                        const float* __restrict__ Wemb,
                        const float* __restrict__ bemb) {
    int idx = blockIdx.x * blockDim.x + threadIdx.x;   // < BS*D
    int c   = idx & (D-1);
    int row = idx >> 6;
    int s   = row & (S-1);
    float acc = bemb[c] + g_pe[s*64 + c];
    const float* xr = x + row * NF;
#pragma unroll
    for (int f = 0; f < NF; f++) acc += xr[f] * Wemb[f*D + c];
    g_h[idx] = acc;
}

// ---------------- 2) fused QKV projection ----------------
__global__ void k_qkv(const float* __restrict__ Wq, const float* __restrict__ bq,
                      const float* __restrict__ Wk, const float* __restrict__ bk,
                      const float* __restrict__ Wv, const float* __restrict__ bv,
                      int l) {
    extern __shared__ float sm[];
    float* sWq  = sm;
    float* sWk  = sm + 4096;
    float* sWv  = sm + 8192;
    float* srow = sm + 12288;         // 16*64 floats
    int tid = threadIdx.x;
    const float* wq = Wq + l*4096;
    const float* wk = Wk + l*4096;
    const float* wv = Wv + l*4096;
    for (int i = tid; i < 4096; i += 256) { sWq[i]=wq[i]; sWk[i]=wk[i]; sWv[i]=wv[i]; }
    int r  = tid >> 4;     // 0..15 row in group
    int cq = tid & 15;     // quad of 4 cols
    float4 bq4 = ((const float4*)(bq + l*D))[cq];
    float4 bk4 = ((const float4*)(bk + l*D))[cq];
    float4 bv4 = ((const float4*)(bv + l*D))[cq];
    ull bq01 = fpack2(bq4.x, bq4.y), bq23 = fpack2(bq4.z, bq4.w);
    ull bk01 = fpack2(bk4.x, bk4.y), bk23 = fpack2(bk4.z, bk4.w);
    ull bv01 = fpack2(bv4.x, bv4.y), bv23 = fpack2(bv4.z, bv4.w);
    const ulonglong2* sWq2 = (const ulonglong2*)sWq;
    const ulonglong2* sWk2 = (const ulonglong2*)sWk;
    const ulonglong2* sWv2 = (const ulonglong2*)sWv;
    __syncthreads();
    for (int g = 0; g < 4; g++) {
        int row0 = blockIdx.x * 64 + g * 16;
        ((float4*)srow)[tid] = ((const float4*)(g_h + row0*D))[tid];
        __syncthreads();
        ull aq01=bq01, aq23=bq23, ak01=bk01, ak23=bk23, av01=bv01, av23=bv23;
        const float* hr = srow + r*64;
#pragma unroll
        for (int i = 0; i < 64; i++) {
            ull apk = fpack2(hr[i], hr[i]);
            ulonglong2 wqv = sWq2[i*16 + cq];
            ulonglong2 wkv = sWk2[i*16 + cq];
            ulonglong2 wvv = sWv2[i*16 + cq];
            aq01 = ffma2(apk, wqv.x, aq01); aq23 = ffma2(apk, wqv.y, aq23);
            ak01 = ffma2(apk, wkv.x, ak01); ak23 = ffma2(apk, wkv.y, ak23);
            av01 = ffma2(apk, wvv.x, av01); av23 = ffma2(apk, wvv.y, av23);
        }
        int row = row0 + r;
        ((ulonglong2*)(g_q + row*D + cq*4))[0] = make_ulonglong2(aq01, aq23);
        ((ulonglong2*)(g_k + row*D + cq*4))[0] = make_ulonglong2(ak01, ak23);
        ((ulonglong2*)(g_v + row*D + cq*4))[0] = make_ulonglong2(av01, av23);
        __syncthreads();
    }
}

// ---------------- 3) attention: packed f32x2, no-max softmax ----------------
__global__ void k_attn() {
    extern __shared__ float sm[];
    float* sK = sm;             // 1024*8
    float* sV = sm + S*HD;
    int tid = threadIdx.x;
    int bh  = blockIdx.y;
    int b   = bh >> 3, hh = bh & 7;
    const float* kbase = g_k + (size_t)(b*S)*D + hh*HD;
    const float* vbase = g_v + (size_t)(b*S)*D + hh*HD;
    for (int t = tid; t < S*HD; t += 256) {
        int s = t >> 3, d = t & 7;
        sK[t] = kbase[s*D + d];
        sV[t] = vbase[s*D + d];
    }
    __syncthreads();

    // 2 queries per thread
    int qi0 = blockIdx.x * 512 + tid;
    int qi1 = qi0 + 256;
    const float pre = 0.35355339059327373f * 1.4426950408889634f;  // scale * log2(e)
    ull qa[4], qb[4];
    {
        const float* qp = g_q + (size_t)(b*S + qi0)*D + hh*HD;
#pragma unroll
        for (int i = 0; i < 4; i++) qa[i] = fpack2(qp[2*i]*pre, qp[2*i+1]*pre);
        qp = g_q + (size_t)(b*S + qi1)*D + hh*HD;
#pragma unroll
        for (int i = 0; i < 4; i++) qb[i] = fpack2(qp[2*i]*pre, qp[2*i+1]*pre);
    }
    ull accA[4] = {0,0,0,0}, accB[4] = {0,0,0,0};
    float lsumA = 0.f, lsumB = 0.f;
    const ulonglong2* K2 = (const ulonglong2*)sK;
    const ulonglong2* V2 = (const ulonglong2*)sV;

#pragma unroll 2
    for (int j = 0; j < S; j++) {
        ulonglong2 k01 = K2[j*2], k23 = K2[j*2+1];
        // dot A
        ull tA = fmul2(qa[0], k01.x);
        tA = ffma2(qa[1], k01.y, tA);
        tA = ffma2(qa[2], k23.x, tA);
        tA = ffma2(qa[3], k23.y, tA);
        float aL, aH; funpack2(tA, aL, aH);
        float wA = fex2(aL + aH);
        // dot B
        ull tB = fmul2(qb[0], k01.x);
        tB = ffma2(qb[1], k01.y, tB);
        tB = ffma2(qb[2], k23.x, tB);
        tB = ffma2(qb[3], k23.y, tB);
        float bL, bH; funpack2(tB, bL, bH);
        float wB = fex2(bL + bH);
        lsumA += wA; lsumB += wB;
        ull wpkA = fpack2(wA, wA), wpkB = fpack2(wB, wB);
        ulonglong2 v01 = V2[j*2], v23 = V2[j*2+1];
        accA[0] = ffma2(wpkA, v01.x, accA[0]);
        accA[1] = ffma2(wpkA, v01.y, accA[1]);
        accA[2] = ffma2(wpkA, v23.x, accA[2]);
        accA[3] = ffma2(wpkA, v23.y, accA[3]);
        accB[0] = ffma2(wpkB, v01.x, accB[0]);
        accB[1] = ffma2(wpkB, v01.y, accB[1]);
        accB[2] = ffma2(wpkB, v23.x, accB[2]);
        accB[3] = ffma2(wpkB, v23.y, accB[3]);
    }
    float invA = 1.0f / lsumA, invB = 1.0f / lsumB;
    ull ipkA = fpack2(invA, invA), ipkB = fpack2(invB, invB);
    {
        float* op = g_ao + (size_t)(b*S + qi0)*D + hh*HD;
        ulonglong2* op2 = (ulonglong2*)op;
        op2[0] = make_ulonglong2(fmul2(accA[0], ipkA), fmul2(accA[1], ipkA));
        op2[1] = make_ulonglong2(fmul2(accA[2], ipkA), fmul2(accA[3], ipkA));
        op = g_ao + (size_t)(b*S + qi1)*D + hh*HD;
        op2 = (ulonglong2*)op;
        op2[0] = make_ulonglong2(fmul2(accB[0], ipkB), fmul2(accB[1], ipkB));
        op2[1] = make_ulonglong2(fmul2(accB[2], ipkB), fmul2(accB[3], ipkB));
    }
}

// ---------------- 4) output projection + residual + LayerNorm1 ----------------
__global__ void k_oproj_ln(const float* __restrict__ Wo, const float* __restrict__ bo,
                           const float* __restrict__ g1, const float* __restrict__ b1,
                           int l) {
    __shared__ float sW[4096];
    __shared__ float satt[1024];
    int tid = threadIdx.x;
    const float* w = Wo + l*4096;
    for (int i = tid; i < 4096; i += 256) sW[i] = w[i];
    int r  = tid >> 4;
    int cq = tid & 15;
    float4 bo4 = ((const float4*)(bo + l*D))[cq];
    float4 gv4 = ((const float4*)(g1 + l*D))[cq];
    float4 bv4 = ((const float4*)(b1 + l*D))[cq];
    ull b01 = fpack2(bo4.x, bo4.y), b23 = fpack2(bo4.z, bo4.w);
    const ulonglong2* sW2 = (const ulonglong2*)sW;
    __syncthreads();
    for (int g = 0; g < 4; g++) {
        int row0 = blockIdx.x * 64 + g * 16;
        ((float4*)satt)[tid] = ((const float4*)(g_ao + row0*D))[tid];
        __syncthreads();
        ull a01 = b01, a23 = b23;
        const float* ar = satt + r*64;
#pragma unroll
        for (int i = 0; i < 64; i++) {
            ull apk = fpack2(ar[i], ar[i]);
            ulonglong2 wv = sW2[i*16 + cq];
            a01 = ffma2(apk, wv.x, a01);
            a23 = ffma2(apk, wv.y, a23);
        }
        int row = row0 + r;
        float4 hres = ((const float4*)(g_h + row*D))[cq];
        float v0, v1, v2, v3;
        funpack2(a01, v0, v1); funpack2(a23, v2, v3);
        v0 += hres.x; v1 += hres.y; v2 += hres.z; v3 += hres.w;
        float sum = v0+v1+v2+v3;
        float sq  = v0*v0+v1*v1+v2*v2+v3*v3;
#pragma unroll
        for (int o = 1; o < 16; o <<= 1) {
            sum += __shfl_xor_sync(0xffffffffu, sum, o);
            sq  += __shfl_xor_sync(0xffffffffu, sq,  o);
        }
        float mean = sum * (1.f/64.f);
        float var  = sq  * (1.f/64.f) - mean*mean;
        float rs = rsqrtf(var + 1e-5f);
        float4 outv;
        outv.x = (v0-mean)*rs*gv4.x + bv4.x;
        outv.y = (v1-mean)*rs*gv4.y + bv4.y;
        outv.z = (v2-mean)*rs*gv4.z + bv4.z;
        outv.w = (v3-mean)*rs*gv4.w + bv4.w;
        ((float4*)(g_h + row*D))[cq] = outv;
        __syncthreads();
    }
}

// ---------------- 5) FFN first matmul + ReLU ----------------
__global__ void k_ffn1(const float* __restrict__ Wf1, const float* __restrict__ bf1, int l) {
    __shared__ float sW[8192];
    __shared__ float srow[2048];      // 32 rows x 64
    int tid = threadIdx.x;
    const float* w = Wf1 + l*8192;
    for (int i = tid; i < 8192; i += 256) sW[i] = w[i];
    int jq = tid & 31;     // quad of FF
    int rb = tid >> 5;     // 0..7 -> 4 rows each
    float4 bf4 = ((const float4*)(bf1 + l*FF))[jq];
    ull bf01 = fpack2(bf4.x, bf4.y), bf23 = fpack2(bf4.z, bf4.w);
    const ulonglong2* sW2 = (const ulonglong2*)sW;
    __syncthreads();
    for (int g = 0; g < 2; g++) {
        int row0 = blockIdx.x * 64 + g * 32;
        ((float4*)srow)[tid]       = ((const float4*)(g_h + row0*D))[tid];
        ((float4*)srow)[tid + 256] = ((const float4*)(g_h + row0*D))[tid + 256];
        __syncthreads();
        ull a01[4], a23[4];
#pragma unroll
        for (int r4 = 0; r4 < 4; r4++) { a01[r4] = bf01; a23[r4] = bf23; }
        const float* hr = srow + (rb*4)*64;
#pragma unroll
        for (int i = 0; i < 64; i++) {
            ulonglong2 wv = sW2[i*32 + jq];
#pragma unroll
            for (int r4 = 0; r4 < 4; r4++) {
                float a = hr[r4*64 + i];
                ull apk = fpack2(a, a);
                a01[r4] = ffma2(apk, wv.x, a01[r4]);
                a23[r4] = ffma2(apk, wv.y, a23[r4]);
            }
        }
#pragma unroll
        for (int r4 = 0; r4 < 4; r4++) {
            int row = row0 + rb*4 + r4;
            float v0,v1,v2,v3;
            funpack2(a01[r4], v0, v1); funpack2(a23[r4], v2, v3);
            float4 ov;
            ov.x = fmaxf(v0, 0.f); ov.y = fmaxf(v1, 0.f);
            ov.z = fmaxf(v2, 0.f); ov.w = fmaxf(v3, 0.f);
            ((float4*)(g_ffh + row*FF))[jq] = ov;
        }
        __syncthreads();
    }
}

// ---------------- 6) FFN second matmul + residual + LayerNorm2 ----------------
__global__ void k_ffn2_ln(const float* __restrict__ Wf2, const float* __restrict__ bf2,
                          const float* __restrict__ g2, const float* __restrict__ b2,
                          int l) {
    extern __shared__ float sm[];
    float* sW   = sm;            // 8192
    float* srow = sm + 8192;     // 32 rows x 128 = 4096
    int tid = threadIdx.x;
    const float* w = Wf2 + l*8192;
    for (int i = tid; i < 8192; i += 256) sW[i] = w[i];
    int cq = tid & 15;     // quad of D
    int rb = tid >> 4;     // 0..15 -> 2 rows each
    float4 bf4 = ((const float4*)(bf2 + l*D))[cq];
    float4 gv4 = ((const float4*)(g2 + l*D))[cq];
    float4 bv4 = ((const float4*)(b2 + l*D))[cq];
    ull b01 = fpack2(bf4.x, bf4.y), b23 = fpack2(bf4.z, bf4.w);
    const ulonglong2* sW2 = (const ulonglong2*)sW;
    __syncthreads();
    for (int g = 0; g < 2; g++) {
        int row0 = blockIdx.x * 64 + g * 32;
#pragma unroll
        for (int t = 0; t < 4; t++)
            ((float4*)srow)[tid + t*256] = ((const float4*)(g_ffh + row0*FF))[tid + t*256];
        __syncthreads();
        ull a01_0 = b01, a23_0 = b23, a01_1 = b01, a23_1 = b23;
        const float* h0 = srow + (rb*2)*128;
        const float* h1 = h0 + 128;
#pragma unroll
        for (int i = 0; i < 128; i++) {
            ulonglong2 wv = sW2[i*16 + cq];
            ull apk0 = fpack2(h0[i], h0[i]);
            ull apk1 = fpack2(h1[i], h1[i]);
            a01_0 = ffma2(apk0, wv.x, a01_0); a23_0 = ffma2(apk0, wv.y, a23_0);
            a01_1 = ffma2(apk1, wv.x, a01_1); a23_1 = ffma2(apk1, wv.y, a23_1);
        }
#pragma unroll
        for (int rr = 0; rr < 2; rr++) {
            int row = row0 + rb*2 + rr;
            ull a01 = rr ? a01_1 : a01_0;
            ull a23 = rr ? a23_1 : a23_0;
            float4 hres = ((const float4*)(g_h + row*D))[cq];
            float v0,v1,v2,v3;
            funpack2(a01, v0, v1); funpack2(a23, v2, v3);
            v0 += hres.x; v1 += hres.y; v2 += hres.z; v3 += hres.w;
            float sum = v0+v1+v2+v3;
            float sq  = v0*v0+v1*v1+v2*v2+v3*v3;
#pragma unroll
            for (int o = 1; o < 16; o <<= 1) {
                sum += __shfl_xor_sync(0xffffffffu, sum, o);
                sq  += __shfl_xor_sync(0xffffffffu, sq,  o);
            }
            float mean = sum * (1.f/64.f);
            float var  = sq  * (1.f/64.f) - mean*mean;
            float rs = rsqrtf(var + 1e-5f);
            float4 outv;
            outv.x = (v0-mean)*rs*gv4.x + bv4.x;
            outv.y = (v1-mean)*rs*gv4.y + bv4.y;
            outv.z = (v2-mean)*rs*gv4.z + bv4.z;
            outv.w = (v3-mean)*rs*gv4.w + bv4.w;
            ((float4*)(g_h + row*D))[cq] = outv;
        }
        __syncthreads();
    }
}

// ---------------- 7) mean pool + MLP head -> angles ----------------
__global__ void k_pool_mlp(const float* __restrict__ Wp1, const float* __restrict__ bp1,
                           const float* __restrict__ Wp2, const float* __restrict__ bp2) {
    __shared__ float sp2[256];
    __shared__ float sp[64];
    __shared__ float sh[32];
    int b = blockIdx.x, tid = threadIdx.x;
    int col = tid & 63, ch = tid >> 6;
    const float* hb = g_h + (size_t)b*S*D + (size_t)ch*256*D;
    float sum = 0.f;
#pragma unroll 8
    for (int s = 0; s < 256; s++) sum += hb[s*D + col];
    sp2[tid] = sum;
    __syncthreads();
    if (tid < 64) {
        sp[tid] = (sp2[tid] + sp2[tid+64] + sp2[tid+128] + sp2[tid+192]) * (1.0f/(float)S);
    }
    __syncthreads();
    if (tid < 32) {
        float a = bp1[tid];
#pragma unroll
        for (int i = 0; i < 64; i++) a += sp[i] * Wp1[i*32 + tid];
        sh[tid] = fmaxf(a, 0.f);
    }
    __syncthreads();
    if (tid < 8) {
        float a = bp2[tid];
#pragma unroll
        for (int i = 0; i < 32; i++) a += sh[i] * Wp2[i*8 + tid];
        g_angles[b*NQ + tid] = tanhf(a) * 3.14159265358979f;
    }
}

// ---------------- 8) quantum circuit + <Z> + entropy ----------------
#define BARS128() asm volatile("bar.sync 1, 128;" ::: "memory")

__global__ void k_quantum(const float* __restrict__ qw, float* __restrict__ out) {
    __shared__ float2 st[256];
    __shared__ float2 rho[256];
    __shared__ float  sred[256];
    __shared__ float  jc[8], js[8], jpx[8], jpy[8];
    int b = blockIdx.x, tid = threadIdx.x;

    st[tid] = make_float2(tid == 0 ? 1.f : 0.f, 0.f);
    float ang[NQ];
#pragma unroll
    for (int w = 0; w < NQ; w++) ang[w] = g_angles[b*NQ + w];

    for (int l = 0; l < QL; l++) {
        for (int w = 0; w < NQ; w++) {
            int mask = 1 << (7 - w);
            float c = cosf(0.5f * ang[w]);
            float s = sinf(0.5f * ang[w]);
            __syncthreads();
            if (!(tid & mask)) {
                float2 v0 = st[tid], v1 = st[tid | mask];
                st[tid]        = make_float2(c*v0.x + s*v1.y,  c*v0.y - s*v1.x);
                st[tid | mask] = make_float2(s*v0.y + c*v1.x, -s*v0.x + c*v1.y);
            }
        }
        for (int w = 0; w < NQ; w++) {
            int mask = 1 << (7 - w);
            float phi = qw[(l*NQ + w)*3 + 0];
            float th  = qw[(l*NQ + w)*3 + 1];
            float om  = qw[(l*NQ + w)*3 + 2];
            float ct = cosf(0.5f*th), stt = sinf(0.5f*th);
            float aa = 0.5f*(phi + om), bb = 0.5f*(phi - om);
            float ca = cosf(aa), sa = sinf(aa), cb = cosf(bb), sb = sinf(bb);
            float2 U00 = make_float2( ct*ca, -ct*sa);
            float2 U01 = make_float2(-stt*cb, -stt*sb);
            float2 U10 = make_float2( stt*cb, -stt*sb);
            float2 U11 = make_float2( ct*ca,  ct*sa);
            __syncthreads();
            if (!(tid & mask)) {
                float2 v0 = st[tid], v1 = st[tid | mask];
                st[tid]        = cadd(cmul(U00, v0), cmul(U01, v1));
                st[tid | mask] = cadd(cmul(U10, v0), cmul(U11, v1));
            }
        }
        for (int w = 0; w < NQ; w++) {
            int mc = 1 << (7 - w);
            int mt = 1 << (7 - ((w + 1) & 7));
            __syncthreads();
            if ((tid & mc) && !(tid & mt)) {
                float2 t0 = st[tid];
                st[tid] = st[tid | mt];
                st[tid | mt] = t0;
            }
        }
    }
    __syncthreads();

    // <Z_w> w=0..2
    float p = st[tid].x*st[tid].x + st[tid].y*st[tid].y;
    for (int w = 0; w < 3; w++) {
        sred[tid] = (tid & (1 << (7 - w))) ? -p : p;
        __syncthreads();
        for (int off = 128; off > 0; off >>= 1) {
            if (tid < off) sred[tid] += sred[tid + off];
            __syncthreads();
        }
        if (tid == 0) out[b*3 + w] = sred[0];
        __syncthreads();
    }

    // rho = mat @ mat^H
    {
        int r = tid >> 4, c = tid & 15;
        float2 acc = make_float2(0.f, 0.f);
#pragma unroll
        for (int k = 0; k < 16; k++) {
            float2 mr = st[r*16 + k], mcv = st[c*16 + k];
            acc.x += mr.x*mcv.x + mr.y*mcv.y;
            acc.y += mr.y*mcv.x - mr.x*mcv.y;
        }
        rho[tid] = acc;
    }
    __syncthreads();

    // parallel tournament Jacobi: 8 disjoint pairs x 16 lanes = 128 threads
    if (tid < 128) {
        int g = tid >> 4, k = tid & 15;
        for (int sweep = 0; sweep < 6; sweep++) {
            for (int rnd = 0; rnd < 15; rnd++) {
                int pa, qa_;
                if (g == 0) { pa = 15; qa_ = rnd; }
                else {
                    pa  = (rnd + g) % 15;
                    qa_ = (rnd + 15 - g) % 15;
                }
                int pp = min(pa, qa_), qq = max(pa, qa_);
                if (k == 0) {
                    float2 apq = rho[pp*16 + qq];
                    float b2 = apq.x*apq.x + apq.y*apq.y;
                    if (b2 > 1e-26f) {
                        float app = rho[pp*16 + pp].x;
                        float aqq = rho[qq*16 + qq].x;
                        float bn  = sqrtf(b2);
                        float tau = (aqq - app) / (2.f * bn);
                        float rt  = sqrtf(1.f + tau*tau);
                        float t   = (tau >= 0.f) ? 1.f/(tau + rt) : -1.f/(-tau + rt);
                        float cc  = rsqrtf(1.f + t*t);
                        jc[g] = cc; js[g] = t*cc;
                        jpx[g] = apq.x/bn; jpy[g] = apq.y/bn;
                    } else {
                        jc[g] = 1.f; js[g] = 0.f; jpx[g] = 1.f; jpy[g] = 0.f;
                    }
                }
                BARS128();
                float cc = jc[g], ss = js[g];
                float2 ph = make_float2(jpx[g], jpy[g]);
                // row update
                {
                    float2 rp = rho[pp*16 + k], rq = rho[qq*16 + k];
                    float2 prq  = cmul(ph, rq);
                    float2 cprp = cmulcj(ph, rp);
                    rho[pp*16 + k] = make_float2(cc*rp.x - ss*prq.x,  cc*rp.y - ss*prq.y);
                    rho[qq*16 + k] = make_float2(ss*cprp.x + cc*rq.x, ss*cprp.y + cc*rq.y);
                }
                BARS128();
                // column update
                {
                    float2 cp = rho[k*16 + pp], cq = rho[k*16 + qq];
                    float2 ccq = cmulcj(ph, cq);
                    float2 pcp = cmul(ph, cp);
                    rho[k*16 + pp] = make_float2(cc*cp.x - ss*ccq.x,  cc*cp.y - ss*ccq.y);
                    rho[k*16 + qq] = make_float2(ss*pcp.x + cc*cq.x, ss*pcp.y + cc*cq.y);
                }
                BARS128();
            }
        }
        if (tid == 0) {
            float ent = 0.f;
#pragma unroll
            for (int kk = 0; kk < 16; kk++) {
                float ev = rho[kk*16 + kk].x;
                ev = fminf(fmaxf(ev, 1e-10f), 1.f);
                ent -= ev * logf(ev);
            }
            out[48 + b] = ent;
        }
    }
}

// ---------------- launch ----------------
extern "C" void kernel_launch(void* const* d_in, const int* in_sizes, int n_in,
                              void* d_out, int out_size) {
    const float* x    = (const float*)d_in[0];
    const float* Wemb = (const float*)d_in[1];
    const float* bemb = (const float*)d_in[2];
    const float* Wq   = (const float*)d_in[3];
    const float* bq   = (const float*)d_in[4];
    const float* Wk   = (const float*)d_in[5];
    const float* bk   = (const float*)d_in[6];
    const float* Wv   = (const float*)d_in[7];
    const float* bv   = (const float*)d_in[8];
    const float* Wo   = (const float*)d_in[9];
    const float* bo   = (const float*)d_in[10];
    const float* ln1g = (const float*)d_in[11];
    const float* ln1b = (const float*)d_in[12];
    const float* ln2g = (const float*)d_in[13];
    const float* ln2b = (const float*)d_in[14];
    const float* Wf1  = (const float*)d_in[15];
    const float* bf1  = (const float*)d_in[16];
    const float* Wf2  = (const float*)d_in[17];
    const float* bf2  = (const float*)d_in[18];
    const float* Wp1  = (const float*)d_in[19];
    const float* bp1  = (const float*)d_in[20];
    const float* Wp2  = (const float*)d_in[21];
    const float* bp2  = (const float*)d_in[22];
    const float* qw   = (const float*)d_in[23];
    float* out = (float*)d_out;

    cudaFuncSetAttribute(k_attn,    cudaFuncAttributeMaxDynamicSharedMemorySize, 65536);
    cudaFuncSetAttribute(k_qkv,     cudaFuncAttributeMaxDynamicSharedMemorySize, 53248);
    cudaFuncSetAttribute(k_ffn2_ln, cudaFuncAttributeMaxDynamicSharedMemorySize, 50176);

    k_pe<<<128, 256>>>();
    k_embed<<<(BS*D)/256, 256>>>(x, Wemb, bemb);
    for (int l = 0; l < NL; l++) {
        k_qkv<<<256, 256, 53248>>>(Wq, bq, Wk, bk, Wv, bv, l);
        dim3 ag(2, B*H);
        k_attn<<<ag, 256, 65536>>>();
        k_oproj_ln<<<256, 256>>>(Wo, bo, ln1g, ln1b, l);
        k_ffn1<<<256, 256>>>(Wf1, bf1, l);
        k_ffn2_ln<<<256, 256, 49152>>>(Wf2, bf2, ln2g, ln2b, l);
    }
    k_pool_mlp<<<B, 256>>>(Wp1, bp1, Wp2, bp2);
    k_quantum<<<B, 256>>>(qw, out);
}

// round 3
// speedup vs baseline: 2.0360x; 1.0212x over previous
#include <cuda_runtime.h>
#include <math.h>

#define B   16
#define S   1024
#define NF  5
#define D   64
#define H   8
#define HD  8
#define NL  2
#define FF  128
#define NQ  8
#define QL  3
#define BS  (B*S)
#define NCHUNK 4
#define CK  (S/NCHUNK)     // 256 keys per chunk

typedef unsigned long long ull;

// ---------------- device scratch ----------------
__device__ float g_h  [BS*D];
__device__ float g_q  [BS*D];
__device__ float g_k  [BS*D];
__device__ float g_v  [BS*D];
__device__ float g_ao [BS*D];
__device__ float g_ffh[BS*FF];
__device__ float g_pe [S*D];
__device__ float g_angles[B*NQ];
__device__ float g_part[(size_t)NCHUNK*128*S*12];   // 25 MB partials

// ---------------- packed f32x2 helpers ----------------
__device__ __forceinline__ ull ffma2(ull a, ull b, ull c) {
    ull d; asm("fma.rn.f32x2 %0, %1, %2, %3;" : "=l"(d) : "l"(a), "l"(b), "l"(c)); return d;
}
__device__ __forceinline__ ull fmul2(ull a, ull b) {
    ull d; asm("mul.rn.f32x2 %0, %1, %2;" : "=l"(d) : "l"(a), "l"(b)); return d;
}
__device__ __forceinline__ ull fpack2(float lo, float hi) {
    ull d; asm("mov.b64 %0, {%1, %2};" : "=l"(d) : "f"(lo), "f"(hi)); return d;
}
__device__ __forceinline__ void funpack2(ull v, float& lo, float& hi) {
    asm("mov.b64 {%0, %1}, %2;" : "=f"(lo), "=f"(hi) : "l"(v));
}
__device__ __forceinline__ float fex2(float x) {
    float r; asm("ex2.approx.f32 %0, %1;" : "=f"(r) : "f"(x)); return r;
}

// ---------------- complex helpers ----------------
__device__ __forceinline__ float2 cmul(float2 a, float2 b) {
    return make_float2(a.x*b.x - a.y*b.y, a.x*b.y + a.y*b.x);
}
__device__ __forceinline__ float2 cmulcj(float2 a, float2 b) {
    return make_float2(a.x*b.x + a.y*b.y, a.x*b.y - a.y*b.x);
}
__device__ __forceinline__ float2 cadd(float2 a, float2 b) {
    return make_float2(a.x + b.x, a.y + b.y);
}

// ---------------- 0) positional-encoding table ----------------
__global__ void k_pe() {
    int idx = blockIdx.x * blockDim.x + threadIdx.x;   // < 32768
    int s = idx >> 5, p = idx & 31;
    float div = __expf(-0.14391156831212787f * (float)(2*p));
    float sn, cs;
    sincosf((float)s * div, &sn, &cs);
    g_pe[s*64 + 2*p]     = sn;
    g_pe[s*64 + 2*p + 1] = cs;
}

// ---------------- 1) embedding ----------------
__global__ void k_embed(const float* __restrict__ x,
                        const float* __restrict__ Wemb,
                        const float* __restrict__ bemb) {
    int idx = blockIdx.x * blockDim.x + threadIdx.x;   // < BS*D
    int c   = idx & (D-1);
    int row = idx >> 6;
    int s   = row & (S-1);
    float acc = bemb[c] + g_pe[s*64 + c];
    const float* xr = x + row * NF;
#pragma unroll
    for (int f = 0; f < NF; f++) acc += xr[f] * Wemb[f*D + c];
    g_h[idx] = acc;
}

// ---------------- 2) fused QKV projection (32 rows / block) ----------------
__global__ void k_qkv(const float* __restrict__ Wq, const float* __restrict__ bq,
                      const float* __restrict__ Wk, const float* __restrict__ bk,
                      const float* __restrict__ Wv, const float* __restrict__ bv,
                      int l) {
    extern __shared__ float sm[];
    float* sWq  = sm;
    float* sWk  = sm + 4096;
    float* sWv  = sm + 8192;
    float* srow = sm + 12288;         // 16*64 floats
    int tid = threadIdx.x;
    const float* wq = Wq + l*4096;
    const float* wk = Wk + l*4096;
    const float* wv = Wv + l*4096;
    for (int i = tid; i < 4096; i += 256) { sWq[i]=wq[i]; sWk[i]=wk[i]; sWv[i]=wv[i]; }
    int r  = tid >> 4;
    int cq = tid & 15;
    float4 bq4 = ((const float4*)(bq + l*D))[cq];
    float4 bk4 = ((const float4*)(bk + l*D))[cq];
    float4 bv4 = ((const float4*)(bv + l*D))[cq];
    ull bq01 = fpack2(bq4.x, bq4.y), bq23 = fpack2(bq4.z, bq4.w);
    ull bk01 = fpack2(bk4.x, bk4.y), bk23 = fpack2(bk4.z, bk4.w);
    ull bv01 = fpack2(bv4.x, bv4.y), bv23 = fpack2(bv4.z, bv4.w);
    const ulonglong2* sWq2 = (const ulonglong2*)sWq;
    const ulonglong2* sWk2 = (const ulonglong2*)sWk;
    const ulonglong2* sWv2 = (const ulonglong2*)sWv;
    __syncthreads();
    for (int g = 0; g < 2; g++) {
        int row0 = blockIdx.x * 32 + g * 16;
        ((float4*)srow)[tid] = ((const float4*)(g_h + row0*D))[tid];
        __syncthreads();
        ull aq01=bq01, aq23=bq23, ak01=bk01, ak23=bk23, av01=bv01, av23=bv23;
        const float* hr = srow + r*64;
#pragma unroll
        for (int i = 0; i < 64; i++) {
            ull apk = fpack2(hr[i], hr[i]);
            ulonglong2 wqv = sWq2[i*16 + cq];
            ulonglong2 wkv = sWk2[i*16 + cq];
            ulonglong2 wvv = sWv2[i*16 + cq];
            aq01 = ffma2(apk, wqv.x, aq01); aq23 = ffma2(apk, wqv.y, aq23);
            ak01 = ffma2(apk, wkv.x, ak01); ak23 = ffma2(apk, wkv.y, ak23);
            av01 = ffma2(apk, wvv.x, av01); av23 = ffma2(apk, wvv.y, av23);
        }
        int row = row0 + r;
        ((ulonglong2*)(g_q + row*D + cq*4))[0] = make_ulonglong2(aq01, aq23);
        ((ulonglong2*)(g_k + row*D + cq*4))[0] = make_ulonglong2(ak01, ak23);
        ((ulonglong2*)(g_v + row*D + cq*4))[0] = make_ulonglong2(av01, av23);
        __syncthreads();
    }
}

// ---------------- 3a) attention partials (split-K) ----------------
// grid: x = qtile(2) * chunk(4) = 8, y = 128 (b*h). 1024 blocks, 16KB smem.
__global__ void k_attn_part() {
    __shared__ float sK[CK*HD];
    __shared__ float sV[CK*HD];
    int tid = threadIdx.x;
    int bh  = blockIdx.y;
    int b   = bh >> 3, hh = bh & 7;
    int qt  = blockIdx.x & 1;
    int ck  = blockIdx.x >> 1;
    int k0  = ck * CK;
    const float* kbase = g_k + (size_t)(b*S + k0)*D + hh*HD;
    const float* vbase = g_v + (size_t)(b*S + k0)*D + hh*HD;
    for (int t = tid; t < CK*HD; t += 256) {
        int s = t >> 3, d = t & 7;
        sK[t] = kbase[s*D + d];
        sV[t] = vbase[s*D + d];
    }
    __syncthreads();

    int qi0 = qt * 512 + tid;
    int qi1 = qi0 + 256;
    const float pre = 0.35355339059327373f * 1.4426950408889634f;  // scale*log2(e)
    ull qa[4], qb[4];
    {
        const float* qp = g_q + (size_t)(b*S + qi0)*D + hh*HD;
#pragma unroll
        for (int i = 0; i < 4; i++) qa[i] = fpack2(qp[2*i]*pre, qp[2*i+1]*pre);
        qp = g_q + (size_t)(b*S + qi1)*D + hh*HD;
#pragma unroll
        for (int i = 0; i < 4; i++) qb[i] = fpack2(qp[2*i]*pre, qp[2*i+1]*pre);
    }
    ull accA[4] = {0,0,0,0}, accB[4] = {0,0,0,0};
    float lsumA = 0.f, lsumB = 0.f;
    const ulonglong2* K2 = (const ulonglong2*)sK;
    const ulonglong2* V2 = (const ulonglong2*)sV;

#pragma unroll 2
    for (int j = 0; j < CK; j++) {
        ulonglong2 k01 = K2[j*2], k23 = K2[j*2+1];
        ull tA = fmul2(qa[0], k01.x);
        tA = ffma2(qa[1], k01.y, tA);
        tA = ffma2(qa[2], k23.x, tA);
        tA = ffma2(qa[3], k23.y, tA);
        float aL, aH; funpack2(tA, aL, aH);
        float wA = fex2(aL + aH);
        ull tB = fmul2(qb[0], k01.x);
        tB = ffma2(qb[1], k01.y, tB);
        tB = ffma2(qb[2], k23.x, tB);
        tB = ffma2(qb[3], k23.y, tB);
        float bL, bH; funpack2(tB, bL, bH);
        float wB = fex2(bL + bH);
        lsumA += wA; lsumB += wB;
        ull wpkA = fpack2(wA, wA), wpkB = fpack2(wB, wB);
        ulonglong2 v01 = V2[j*2], v23 = V2[j*2+1];
        accA[0] = ffma2(wpkA, v01.x, accA[0]);
        accA[1] = ffma2(wpkA, v01.y, accA[1]);
        accA[2] = ffma2(wpkA, v23.x, accA[2]);
        accA[3] = ffma2(wpkA, v23.y, accA[3]);
        accB[0] = ffma2(wpkB, v01.x, accB[0]);
        accB[1] = ffma2(wpkB, v01.y, accB[1]);
        accB[2] = ffma2(wpkB, v23.x, accB[2]);
        accB[3] = ffma2(wpkB, v23.y, accB[3]);
    }
    // store partials (unnormalized) : [ck][bh][q][12]
    {
        float* pp = g_part + (((size_t)ck*128 + bh)*S + qi0)*12;
        float a0,a1,a2,a3,a4,a5,a6,a7;
        funpack2(accA[0],a0,a1); funpack2(accA[1],a2,a3);
        funpack2(accA[2],a4,a5); funpack2(accA[3],a6,a7);
        ((float4*)pp)[0] = make_float4(a0,a1,a2,a3);
        ((float4*)pp)[1] = make_float4(a4,a5,a6,a7);
        pp[8] = lsumA;
        pp = g_part + (((size_t)ck*128 + bh)*S + qi1)*12;
        funpack2(accB[0],a0,a1); funpack2(accB[1],a2,a3);
        funpack2(accB[2],a4,a5); funpack2(accB[3],a6,a7);
        ((float4*)pp)[0] = make_float4(a0,a1,a2,a3);
        ((float4*)pp)[1] = make_float4(a4,a5,a6,a7);
        pp[8] = lsumB;
    }
}

// ---------------- 3b) attention combine ----------------
// grid: x = 4 (q blocks of 256), y = 128 (bh)
__global__ void k_attn_comb() {
    int bh = blockIdx.y;
    int b  = bh >> 3, hh = bh & 7;
    int q  = blockIdx.x * 256 + threadIdx.x;
    float4 s0 = make_float4(0,0,0,0), s1 = make_float4(0,0,0,0);
    float ls = 0.f;
#pragma unroll
    for (int ck = 0; ck < NCHUNK; ck++) {
        const float* pp = g_part + (((size_t)ck*128 + bh)*S + q)*12;
        float4 p0 = ((const float4*)pp)[0];
        float4 p1 = ((const float4*)pp)[1];
        s0.x += p0.x; s0.y += p0.y; s0.z += p0.z; s0.w += p0.w;
        s1.x += p1.x; s1.y += p1.y; s1.z += p1.z; s1.w += p1.w;
        ls += pp[8];
    }
    float inv = 1.0f / ls;
    float* op = g_ao + (size_t)(b*S + q)*D + hh*HD;
    ((float4*)op)[0] = make_float4(s0.x*inv, s0.y*inv, s0.z*inv, s0.w*inv);
    ((float4*)op)[1] = make_float4(s1.x*inv, s1.y*inv, s1.z*inv, s1.w*inv);
}

// ---------------- 4) output projection + residual + LN1 (32 rows/block) ----------------
__global__ void k_oproj_ln(const float* __restrict__ Wo, const float* __restrict__ bo,
                           const float* __restrict__ g1, const float* __restrict__ b1,
                           int l) {
    __shared__ float sW[4096];
    __shared__ float satt[1024];
    int tid = threadIdx.x;
    const float* w = Wo + l*4096;
    for (int i = tid; i < 4096; i += 256) sW[i] = w[i];
    int r  = tid >> 4;
    int cq = tid & 15;
    float4 bo4 = ((const float4*)(bo + l*D))[cq];
    float4 gv4 = ((const float4*)(g1 + l*D))[cq];
    float4 bv4 = ((const float4*)(b1 + l*D))[cq];
    ull b01 = fpack2(bo4.x, bo4.y), b23 = fpack2(bo4.z, bo4.w);
    const ulonglong2* sW2 = (const ulonglong2*)sW;
    __syncthreads();
    for (int g = 0; g < 2; g++) {
        int row0 = blockIdx.x * 32 + g * 16;
        ((float4*)satt)[tid] = ((const float4*)(g_ao + row0*D))[tid];
        __syncthreads();
        ull a01 = b01, a23 = b23;
        const float* ar = satt + r*64;
#pragma unroll
        for (int i = 0; i < 64; i++) {
            ull apk = fpack2(ar[i], ar[i]);
            ulonglong2 wv = sW2[i*16 + cq];
            a01 = ffma2(apk, wv.x, a01);
            a23 = ffma2(apk, wv.y, a23);
        }
        int row = row0 + r;
        float4 hres = ((const float4*)(g_h + row*D))[cq];
        float v0, v1, v2, v3;
        funpack2(a01, v0, v1); funpack2(a23, v2, v3);
        v0 += hres.x; v1 += hres.y; v2 += hres.z; v3 += hres.w;
        float sum = v0+v1+v2+v3;
        float sq  = v0*v0+v1*v1+v2*v2+v3*v3;
#pragma unroll
        for (int o = 1; o < 16; o <<= 1) {
            sum += __shfl_xor_sync(0xffffffffu, sum, o);
            sq  += __shfl_xor_sync(0xffffffffu, sq,  o);
        }
        float mean = sum * (1.f/64.f);
        float var  = sq  * (1.f/64.f) - mean*mean;
        float rs = rsqrtf(var + 1e-5f);
        float4 outv;
        outv.x = (v0-mean)*rs*gv4.x + bv4.x;
        outv.y = (v1-mean)*rs*gv4.y + bv4.y;
        outv.z = (v2-mean)*rs*gv4.z + bv4.z;
        outv.w = (v3-mean)*rs*gv4.w + bv4.w;
        ((float4*)(g_h + row*D))[cq] = outv;
        __syncthreads();
    }
}

// ---------------- 5) FFN first matmul + ReLU (32 rows/block) ----------------
__global__ void k_ffn1(const float* __restrict__ Wf1, const float* __restrict__ bf1, int l) {
    __shared__ float sW[8192];
    __shared__ float srow[2048];      // 32 rows x 64
    int tid = threadIdx.x;
    const float* w = Wf1 + l*8192;
    for (int i = tid; i < 8192; i += 256) sW[i] = w[i];
    int jq = tid & 31;
    int rb = tid >> 5;
    float4 bf4 = ((const float4*)(bf1 + l*FF))[jq];
    ull bf01 = fpack2(bf4.x, bf4.y), bf23 = fpack2(bf4.z, bf4.w);
    const ulonglong2* sW2 = (const ulonglong2*)sW;
    int row0 = blockIdx.x * 32;
    ((float4*)srow)[tid]       = ((const float4*)(g_h + row0*D))[tid];
    ((float4*)srow)[tid + 256] = ((const float4*)(g_h + row0*D))[tid + 256];
    __syncthreads();
    ull a01[4], a23[4];
#pragma unroll
    for (int r4 = 0; r4 < 4; r4++) { a01[r4] = bf01; a23[r4] = bf23; }
    const float* hr = srow + (rb*4)*64;
#pragma unroll
    for (int i = 0; i < 64; i++) {
        ulonglong2 wv = sW2[i*32 + jq];
#pragma unroll
        for (int r4 = 0; r4 < 4; r4++) {
            float a = hr[r4*64 + i];
            ull apk = fpack2(a, a);
            a01[r4] = ffma2(apk, wv.x, a01[r4]);
            a23[r4] = ffma2(apk, wv.y, a23[r4]);
        }
    }
#pragma unroll
    for (int r4 = 0; r4 < 4; r4++) {
        int row = row0 + rb*4 + r4;
        float v0,v1,v2,v3;
        funpack2(a01[r4], v0, v1); funpack2(a23[r4], v2, v3);
        float4 ov;
        ov.x = fmaxf(v0, 0.f); ov.y = fmaxf(v1, 0.f);
        ov.z = fmaxf(v2, 0.f); ov.w = fmaxf(v3, 0.f);
        ((float4*)(g_ffh + row*FF))[jq] = ov;
    }
}

// ---------------- 6) FFN second matmul + residual + LN2 (32 rows/block) ----------------
__global__ void k_ffn2_ln(const float* __restrict__ Wf2, const float* __restrict__ bf2,
                          const float* __restrict__ g2, const float* __restrict__ b2,
                          int l) {
    extern __shared__ float sm[];
    float* sW   = sm;            // 8192
    float* srow = sm + 8192;     // 32 rows x 128 = 4096
    int tid = threadIdx.x;
    const float* w = Wf2 + l*8192;
    for (int i = tid; i < 8192; i += 256) sW[i] = w[i];
    int cq = tid & 15;
    int rb = tid >> 4;
    float4 bf4 = ((const float4*)(bf2 + l*D))[cq];
    float4 gv4 = ((const float4*)(g2 + l*D))[cq];
    float4 bv4 = ((const float4*)(b2 + l*D))[cq];
    ull b01 = fpack2(bf4.x, bf4.y), b23 = fpack2(bf4.z, bf4.w);
    const ulonglong2* sW2 = (const ulonglong2*)sW;
    int row0 = blockIdx.x * 32;
#pragma unroll
    for (int t = 0; t < 4; t++)
        ((float4*)srow)[tid + t*256] = ((const float4*)(g_ffh + row0*FF))[tid + t*256];
    __syncthreads();
    ull a01_0 = b01, a23_0 = b23, a01_1 = b01, a23_1 = b23;
    const float* h0 = srow + (rb*2)*128;
    const float* h1 = h0 + 128;
#pragma unroll
    for (int i = 0; i < 128; i++) {
        ulonglong2 wv = sW2[i*16 + cq];
        ull apk0 = fpack2(h0[i], h0[i]);
        ull apk1 = fpack2(h1[i], h1[i]);
        a01_0 = ffma2(apk0, wv.x, a01_0); a23_0 = ffma2(apk0, wv.y, a23_0);
        a01_1 = ffma2(apk1, wv.x, a01_1); a23_1 = ffma2(apk1, wv.y, a23_1);
    }
#pragma unroll
    for (int rr = 0; rr < 2; rr++) {
        int row = row0 + rb*2 + rr;
        ull a01 = rr ? a01_1 : a01_0;
        ull a23 = rr ? a23_1 : a23_0;
        float4 hres = ((const float4*)(g_h + row*D))[cq];
        float v0,v1,v2,v3;
        funpack2(a01, v0, v1); funpack2(a23, v2, v3);
        v0 += hres.x; v1 += hres.y; v2 += hres.z; v3 += hres.w;
        float sum = v0+v1+v2+v3;
        float sq  = v0*v0+v1*v1+v2*v2+v3*v3;
#pragma unroll
        for (int o = 1; o < 16; o <<= 1) {
            sum += __shfl_xor_sync(0xffffffffu, sum, o);
            sq  += __shfl_xor_sync(0xffffffffu, sq,  o);
        }
        float mean = sum * (1.f/64.f);
        float var  = sq  * (1.f/64.f) - mean*mean;
        float rs = rsqrtf(var + 1e-5f);
        float4 outv;
        outv.x = (v0-mean)*rs*gv4.x + bv4.x;
        outv.y = (v1-mean)*rs*gv4.y + bv4.y;
        outv.z = (v2-mean)*rs*gv4.z + bv4.z;
        outv.w = (v3-mean)*rs*gv4.w + bv4.w;
        ((float4*)(g_h + row*D))[cq] = outv;
    }
}

// ---------------- 7) mean pool + MLP head -> angles ----------------
__global__ void k_pool_mlp(const float* __restrict__ Wp1, const float* __restrict__ bp1,
                           const float* __restrict__ Wp2, const float* __restrict__ bp2) {
    __shared__ float sp2[256];
    __shared__ float sp[64];
    __shared__ float sh[32];
    int b = blockIdx.x, tid = threadIdx.x;
    int col = tid & 63, ch = tid >> 6;
    const float* hb = g_h + (size_t)b*S*D + (size_t)ch*256*D;
    float sum = 0.f;
#pragma unroll 8
    for (int s = 0; s < 256; s++) sum += hb[s*D + col];
    sp2[tid] = sum;
    __syncthreads();
    if (tid < 64) {
        sp[tid] = (sp2[tid] + sp2[tid+64] + sp2[tid+128] + sp2[tid+192]) * (1.0f/(float)S);
    }
    __syncthreads();
    if (tid < 32) {
        float a = bp1[tid];
#pragma unroll
        for (int i = 0; i < 64; i++) a += sp[i] * Wp1[i*32 + tid];
        sh[tid] = fmaxf(a, 0.f);
    }
    __syncthreads();
    if (tid < 8) {
        float a = bp2[tid];
#pragma unroll
        for (int i = 0; i < 32; i++) a += sh[i] * Wp2[i*8 + tid];
        g_angles[b*NQ + tid] = tanhf(a) * 3.14159265358979f;
    }
}

// ---------------- 8) quantum circuit + <Z> + entropy ----------------
#define BARS128() asm volatile("bar.sync 1, 128;" ::: "memory")

__global__ void k_quantum(const float* __restrict__ qw, float* __restrict__ out) {
    __shared__ float2 st[256];
    __shared__ float2 rho[256];
    __shared__ float  sred[256];
    __shared__ float  jc[8], js[8], jpx[8], jpy[8];
    int b = blockIdx.x, tid = threadIdx.x;

    st[tid] = make_float2(tid == 0 ? 1.f : 0.f, 0.f);
    float ang[NQ];
#pragma unroll
    for (int w = 0; w < NQ; w++) ang[w] = g_angles[b*NQ + w];

    for (int l = 0; l < QL; l++) {
        for (int w = 0; w < NQ; w++) {
            int mask = 1 << (7 - w);
            float c = cosf(0.5f * ang[w]);
            float s = sinf(0.5f * ang[w]);
            __syncthreads();
            if (!(tid & mask)) {
                float2 v0 = st[tid], v1 = st[tid | mask];
                st[tid]        = make_float2(c*v0.x + s*v1.y,  c*v0.y - s*v1.x);
                st[tid | mask] = make_float2(s*v0.y + c*v1.x, -s*v0.x + c*v1.y);
            }
        }
        for (int w = 0; w < NQ; w++) {
            int mask = 1 << (7 - w);
            float phi = qw[(l*NQ + w)*3 + 0];
            float th  = qw[(l*NQ + w)*3 + 1];
            float om  = qw[(l*NQ + w)*3 + 2];
            float ct = cosf(0.5f*th), stt = sinf(0.5f*th);
            float aa = 0.5f*(phi + om), bb = 0.5f*(phi - om);
            float ca = cosf(aa), sa = sinf(aa), cb = cosf(bb), sb = sinf(bb);
            float2 U00 = make_float2( ct*ca, -ct*sa);
            float2 U01 = make_float2(-stt*cb, -stt*sb);
            float2 U10 = make_float2( stt*cb, -stt*sb);
            float2 U11 = make_float2( ct*ca,  ct*sa);
            __syncthreads();
            if (!(tid & mask)) {
                float2 v0 = st[tid], v1 = st[tid | mask];
                st[tid]        = cadd(cmul(U00, v0), cmul(U01, v1));
                st[tid | mask] = cadd(cmul(U10, v0), cmul(U11, v1));
            }
        }
        for (int w = 0; w < NQ; w++) {
            int mc = 1 << (7 - w);
            int mt = 1 << (7 - ((w + 1) & 7));
            __syncthreads();
            if ((tid & mc) && !(tid & mt)) {
                float2 t0 = st[tid];
                st[tid] = st[tid | mt];
                st[tid | mt] = t0;
            }
        }
    }
    __syncthreads();

    float p = st[tid].x*st[tid].x + st[tid].y*st[tid].y;
    for (int w = 0; w < 3; w++) {
        sred[tid] = (tid & (1 << (7 - w))) ? -p : p;
        __syncthreads();
        for (int off = 128; off > 0; off >>= 1) {
            if (tid < off) sred[tid] += sred[tid + off];
            __syncthreads();
        }
        if (tid == 0) out[b*3 + w] = sred[0];
        __syncthreads();
    }

    {
        int r = tid >> 4, c = tid & 15;
        float2 acc = make_float2(0.f, 0.f);
#pragma unroll
        for (int k = 0; k < 16; k++) {
            float2 mr = st[r*16 + k], mcv = st[c*16 + k];
            acc.x += mr.x*mcv.x + mr.y*mcv.y;
            acc.y += mr.y*mcv.x - mr.x*mcv.y;
        }
        rho[tid] = acc;
    }
    __syncthreads();

    if (tid < 128) {
        int g = tid >> 4, k = tid & 15;
        for (int sweep = 0; sweep < 6; sweep++) {
            for (int rnd = 0; rnd < 15; rnd++) {
                int pa, qa_;
                if (g == 0) { pa = 15; qa_ = rnd; }
                else {
                    pa  = (rnd + g) % 15;
                    qa_ = (rnd + 15 - g) % 15;
                }
                int pp = min(pa, qa_), qq = max(pa, qa_);
                if (k == 0) {
                    float2 apq = rho[pp*16 + qq];
                    float b2 = apq.x*apq.x + apq.y*apq.y;
                    if (b2 > 1e-26f) {
                        float app = rho[pp*16 + pp].x;
                        float aqq = rho[qq*16 + qq].x;
                        float bn  = sqrtf(b2);
                        float tau = (aqq - app) / (2.f * bn);
                        float rt  = sqrtf(1.f + tau*tau);
                        float t   = (tau >= 0.f) ? 1.f/(tau + rt) : -1.f/(-tau + rt);
                        float cc  = rsqrtf(1.f + t*t);
                        jc[g] = cc; js[g] = t*cc;
                        jpx[g] = apq.x/bn; jpy[g] = apq.y/bn;
                    } else {
                        jc[g] = 1.f; js[g] = 0.f; jpx[g] = 1.f; jpy[g] = 0.f;
                    }
                }
                BARS128();
                float cc = jc[g], ss = js[g];
                float2 ph = make_float2(jpx[g], jpy[g]);
                {
                    float2 rp = rho[pp*16 + k], rq = rho[qq*16 + k];
                    float2 prq  = cmul(ph, rq);
                    float2 cprp = cmulcj(ph, rp);
                    rho[pp*16 + k] = make_float2(cc*rp.x - ss*prq.x,  cc*rp.y - ss*prq.y);
                    rho[qq*16 + k] = make_float2(ss*cprp.x + cc*rq.x, ss*cprp.y + cc*rq.y);
                }
                BARS128();
                {
                    float2 cp = rho[k*16 + pp], cq = rho[k*16 + qq];
                    float2 ccq = cmulcj(ph, cq);
                    float2 pcp = cmul(ph, cp);
                    rho[k*16 + pp] = make_float2(cc*cp.x - ss*ccq.x,  cc*cp.y - ss*ccq.y);
                    rho[k*16 + qq] = make_float2(ss*pcp.x + cc*cq.x, ss*pcp.y + cc*cq.y);
                }
                BARS128();
            }
        }
        if (tid == 0) {
            float ent = 0.f;
#pragma unroll
            for (int kk = 0; kk < 16; kk++) {
                float ev = rho[kk*16 + kk].x;
                ev = fminf(fmaxf(ev, 1e-10f), 1.f);
                ent -= ev * logf(ev);
            }
            out[48 + b] = ent;
        }
    }
}

// ---------------- launch ----------------
extern "C" void kernel_launch(void* const* d_in, const int* in_sizes, int n_in,
                              void* d_out, int out_size) {
    const float* x    = (const float*)d_in[0];
    const float* Wemb = (const float*)d_in[1];
    const float* bemb = (const float*)d_in[2];
    const float* Wq   = (const float*)d_in[3];
    const float* bq   = (const float*)d_in[4];
    const float* Wk   = (const float*)d_in[5];
    const float* bk   = (const float*)d_in[6];
    const float* Wv   = (const float*)d_in[7];
    const float* bv   = (const float*)d_in[8];
    const float* Wo   = (const float*)d_in[9];
    const float* bo   = (const float*)d_in[10];
    const float* ln1g = (const float*)d_in[11];
    const float* ln1b = (const float*)d_in[12];
    const float* ln2g = (const float*)d_in[13];
    const float* ln2b = (const float*)d_in[14];
    const float* Wf1  = (const float*)d_in[15];
    const float* bf1  = (const float*)d_in[16];
    const float* Wf2  = (const float*)d_in[17];
    const float* bf2  = (const float*)d_in[18];
    const float* Wp1  = (const float*)d_in[19];
    const float* bp1  = (const float*)d_in[20];
    const float* Wp2  = (const float*)d_in[21];
    const float* bp2  = (const float*)d_in[22];
    const float* qw   = (const float*)d_in[23];
    float* out = (float*)d_out;

    cudaFuncSetAttribute(k_qkv,     cudaFuncAttributeMaxDynamicSharedMemorySize, 53248);
    cudaFuncSetAttribute(k_ffn2_ln, cudaFuncAttributeMaxDynamicSharedMemorySize, 50176);

    k_pe<<<128, 256>>>();
    k_embed<<<(BS*D)/256, 256>>>(x, Wemb, bemb);
    for (int l = 0; l < NL; l++) {
        k_qkv<<<512, 256, 53248>>>(Wq, bq, Wk, bk, Wv, bv, l);
        dim3 pg(2*NCHUNK, B*H);
        k_attn_part<<<pg, 256>>>();
        dim3 cg(4, B*H);
        k_attn_comb<<<cg, 256>>>();
        k_oproj_ln<<<512, 256>>>(Wo, bo, ln1g, ln1b, l);
        k_ffn1<<<512, 256>>>(Wf1, bf1, l);
        k_ffn2_ln<<<512, 256, 49152>>>(Wf2, bf2, ln2g, ln2b, l);
    }
    k_pool_mlp<<<B, 256>>>(Wp1, bp1, Wp2, bp2);
    k_quantum<<<B, 256>>>(qw, out);
}